// round 1
// baseline (speedup 1.0000x reference)
#include <cuda_runtime.h>

// CombinedPriorityLoss: 0.1*MSE + 0.9*pairwise-rank + 0.1*diversity
//
// Ranking term rewritten over ORDERED pairs (symmetric, diagonal = 0):
//   upper_sum = 0.5 * sum_{all i,j} per_pair(i,j)
// per_pair:
//   dt >  M : relu(M - dp)
//   dt < -M : relu(M + dp)
//   else    : 0.1*|dp|
// Both outer branches = relu(M + qx) with qx = (dt>M ? -dp : dp).
// Mid branch accumulates |dp| into a separate accumulator; 0.1 applied once.

#define MARGIN 0.2f

constexpr int T = 256;              // tile size == block size
constexpr int MAXB = 65536;         // up to nt=256 tiles -> N <= 65536

__device__ float2 g_partial[MAXB];  // (accA, accB) per block, written (not atomically added)

__global__ void pair_kernel(const float* __restrict__ pred,
                            const float* __restrict__ tgt, int N) {
    const int tj = blockIdx.x;
    const int ti = blockIdx.y;
    const int bid = blockIdx.y * gridDim.x + blockIdx.x;
    const int tid = threadIdx.x;

    __shared__ float2 s[T];     // (-pred[j], -tgt[j]) pre-negated
    __shared__ float2 red[8];

    float accA = 0.f, accB = 0.f;

    if (ti <= tj) {             // uniform per block
        int j = tj * T + tid;
        // padding value 1e30 makes every branch contribute exactly 0:
        //  real i, pad j: dt = ti - 1e30 < -M -> relu(M + (pi - 1e30)) = 0
        //  pad i, real j: dt = 1e30 - tj >  M -> relu(M - (1e30 - pj)) = 0
        //  pad i, pad j : dp = dt = 0 -> mid adds |0| = 0
        float pj = (j < N) ? pred[j] : 1e30f;
        float tv = (j < N) ? tgt[j]  : 1e30f;
        s[tid] = make_float2(-pj, -tv);
        __syncthreads();

        int i = ti * T + tid;
        float pi  = (i < N) ? pred[i] : 1e30f;
        float tiv = (i < N) ? tgt[i]  : 1e30f;

        #pragma unroll 8
        for (int jj = 0; jj < T; jj++) {
            float2 v = s[jj];
            float dp = pi + v.x;                       // pred_i - pred_j
            float dt = tiv + v.y;                      // tgt_i  - tgt_j
            float qx = (dt > MARGIN) ? -dp : dp;       // FSETP + FSEL
            float r  = fmaxf(MARGIN + qx, 0.f);        // FADD + FMNMX
            if (fabsf(dt) > MARGIN) accA += r;         // FSETP(|dt|) + @P FADD
            else                    accB += fabsf(dp); // @!P FADD (|dp| free modifier)
        }
        // off-diagonal tile covers (i,j) and mirrored (j,i) ordered pairs
        float w = (ti == tj) ? 1.f : 2.f;
        accA *= w; accB *= w;
    }
    __syncthreads();

    // block reduction (all threads participate; skipped blocks contribute 0)
    const int lane = tid & 31;
    const int wid  = tid >> 5;
    #pragma unroll
    for (int o = 16; o; o >>= 1) {
        accA += __shfl_down_sync(0xffffffffu, accA, o);
        accB += __shfl_down_sync(0xffffffffu, accB, o);
    }
    if (lane == 0) red[wid] = make_float2(accA, accB);
    __syncthreads();
    if (wid == 0) {
        float a = (lane < 8) ? red[lane].x : 0.f;
        float b = (lane < 8) ? red[lane].y : 0.f;
        #pragma unroll
        for (int o = 4; o; o >>= 1) {
            a += __shfl_down_sync(0xffffffffu, a, o);
            b += __shfl_down_sync(0xffffffffu, b, o);
        }
        if (lane == 0) g_partial[bid] = make_float2(a, b);
    }
}

// Single-block epilogue: O(N) moments + reduce pairwise partials + final scalar.
__global__ void finalize_kernel(const float* __restrict__ pred,
                                const float* __restrict__ tgt,
                                int N, int nblocks, float* __restrict__ out) {
    const int tid = threadIdx.x;
    const int nthreads = blockDim.x;

    double sd2 = 0.0, sp = 0.0, spp = 0.0, st = 0.0, stt = 0.0;
    for (int i = tid; i < N; i += nthreads) {
        double p = (double)pred[i];
        double t = (double)tgt[i];
        double d = p - t;
        sd2 += d * d;
        sp  += p;  spp += p * p;
        st  += t;  stt += t * t;
    }
    double aA = 0.0, aB = 0.0;
    for (int b = tid; b < nblocks; b += nthreads) {
        float2 v = g_partial[b];
        aA += (double)v.x;
        aB += (double)v.y;
    }

    // block-wide reduction of 7 doubles
    __shared__ double sh[16][7];
    const int lane = tid & 31, wid = tid >> 5;
    double vals[7] = {sd2, sp, spp, st, stt, aA, aB};
    #pragma unroll
    for (int k = 0; k < 7; k++) {
        double v = vals[k];
        #pragma unroll
        for (int o = 16; o; o >>= 1) v += __shfl_down_sync(0xffffffffu, v, o);
        if (lane == 0) sh[wid][k] = v;
    }
    __syncthreads();
    if (tid == 0) {
        int nw = (nthreads + 31) >> 5;
        double r[7];
        #pragma unroll
        for (int k = 0; k < 7; k++) {
            double v = 0.0;
            for (int w = 0; w < nw; w++) v += sh[w][k];
            r[k] = v;
        }
        double n = (double)N;
        double mse = r[0] / n;
        double pred_var = (r[2] - r[1] * r[1] / n) / (n - 1.0);
        double tgt_var  = (r[4] - r[3] * r[3] / n) / (n - 1.0);
        double div = tgt_var - pred_var;
        if (div < 0.0) div = 0.0;
        long long pc = (long long)N * (N - 1) / 2;
        if (pc < 1) pc = 1;
        double rank = 0.5 * (r[5] + 0.1 * r[6]) / (double)pc;
        out[0] = (float)(0.1 * mse + 0.9 * rank + 0.1 * div);
    }
}

extern "C" void kernel_launch(void* const* d_in, const int* in_sizes, int n_in,
                              void* d_out, int out_size) {
    const float* pred = (const float*)d_in[0];
    const float* tgt  = (const float*)d_in[1];
    float* out = (float*)d_out;
    int N = in_sizes[0];
    int nt = (N + T - 1) / T;
    dim3 grid(nt, nt);
    pair_kernel<<<grid, T>>>(pred, tgt, N);
    finalize_kernel<<<1, 512>>>(pred, tgt, N, nt * nt, out);
}

// round 2
// speedup vs baseline: 1.7554x; 1.7554x over previous
#include <cuda_runtime.h>

// CombinedPriorityLoss: 0.1*MSE + 0.9*pairwise-rank + 0.1*diversity
// Single fused kernel:
//  - tile (ti,tj), ti<=tj active: ordered-pair ranking sums (weight 2 off-diag)
//  - diagonal blocks also compute O(N) moment partials (fp32)
//  - last-finishing block reduces all partials in FIXED order (deterministic)
//    and writes the final scalar; resets the ticket counter for graph replay.

#define MARGIN 0.2f

constexpr int T = 256;            // tile size == block size
constexpr int MAXT = 256;         // max tiles per dim (N <= 65536)
constexpr int MAXB = MAXT * MAXT;

__device__ float2 g_partial[MAXB];        // (accA, accB) per block
__device__ float  g_moms[MAXT][5];        // per diagonal tile: sd2, sp, spp, st, stt
__device__ unsigned g_ticket = 0;

__global__ __launch_bounds__(T)
void fused_kernel(const float* __restrict__ pred,
                  const float* __restrict__ tgt,
                  int N, float* __restrict__ out) {
    const int tj = blockIdx.x;
    const int ti = blockIdx.y;
    const int nt = gridDim.x;
    const int nblocks = nt * nt;
    const int bid = ti * nt + tj;
    const int tid = threadIdx.x;
    const int lane = tid & 31;
    const int wid  = tid >> 5;

    __shared__ float2 s[T];       // (-pred[j], -tgt[j])
    __shared__ float  red[8][8];  // reduction scratch
    __shared__ int    s_last;

    float accA = 0.f, accB = 0.f;

    if (ti <= tj) {
        int j = tj * T + tid;
        // pad 1e30: every branch contributes exactly 0 for padded lanes
        float pj = (j < N) ? pred[j] : 1e30f;
        float tv = (j < N) ? tgt[j]  : 1e30f;
        s[tid] = make_float2(-pj, -tv);
        __syncthreads();

        int i = ti * T + tid;
        float pi  = (i < N) ? pred[i] : 1e30f;
        float tiv = (i < N) ? tgt[i]  : 1e30f;

        #pragma unroll 8
        for (int jj = 0; jj < T; jj++) {
            float2 v = s[jj];
            float dp = pi + v.x;                        // pred_i - pred_j
            float dt = tiv + v.y;                       // tgt_i - tgt_j
            float qx = (dt > MARGIN) ? -dp : dp;
            float r  = fmaxf(MARGIN + qx, 0.f);
            if (fabsf(dt) > MARGIN) accA += r;
            else                    accB += fabsf(dp);
        }
        float w = (ti == tj) ? 1.f : 2.f;
        accA *= w; accB *= w;
    }
    __syncthreads();

    // block reduction of accA/accB
    #pragma unroll
    for (int o = 16; o; o >>= 1) {
        accA += __shfl_down_sync(0xffffffffu, accA, o);
        accB += __shfl_down_sync(0xffffffffu, accB, o);
    }
    if (lane == 0) { red[wid][0] = accA; red[wid][1] = accB; }
    __syncthreads();
    if (tid == 0) {
        float a = 0.f, b = 0.f;
        #pragma unroll
        for (int w2 = 0; w2 < 8; w2++) { a += red[w2][0]; b += red[w2][1]; }
        g_partial[bid] = make_float2(a, b);
    }
    __syncthreads();

    // diagonal blocks: O(N) moment partials (fp32)
    if (ti == tj) {
        int i = ti * T + tid;
        float p = 0.f, t = 0.f;
        if (i < N) { p = pred[i]; t = tgt[i]; }
        float d = p - t;
        float m[5] = { d * d, p, p * p, t, t * t };
        #pragma unroll
        for (int k = 0; k < 5; k++) {
            float v = m[k];
            #pragma unroll
            for (int o = 16; o; o >>= 1) v += __shfl_down_sync(0xffffffffu, v, o);
            if (lane == 0) red[wid][k] = v;
        }
        __syncthreads();
        if (tid == 0) {
            #pragma unroll
            for (int k = 0; k < 5; k++) {
                float v = 0.f;
                #pragma unroll
                for (int w2 = 0; w2 < 8; w2++) v += red[w2][k];
                g_moms[ti][k] = v;
            }
        }
    }

    // ---- deterministic last-block finalize ----
    __threadfence();
    if (tid == 0) {
        unsigned t = atomicAdd(&g_ticket, 1u);
        s_last = (t == (unsigned)(nblocks - 1));
    }
    __syncthreads();
    if (!s_last) return;

    // Last block: reduce everything in fixed index order.
    double aA = 0.0, aB = 0.0;
    for (int b = tid; b < nblocks; b += T) {
        float2 v = g_partial[b];
        aA += (double)v.x; aB += (double)v.y;
    }
    double mm[5] = {0, 0, 0, 0, 0};
    for (int b = tid; b < nt; b += T) {
        #pragma unroll
        for (int k = 0; k < 5; k++) mm[k] += (double)g_moms[b][k];
    }

    __shared__ double dred[8][7];
    double vals[7] = { aA, aB, mm[0], mm[1], mm[2], mm[3], mm[4] };
    #pragma unroll
    for (int k = 0; k < 7; k++) {
        double v = vals[k];
        #pragma unroll
        for (int o = 16; o; o >>= 1) v += __shfl_down_sync(0xffffffffu, v, o);
        if (lane == 0) dred[wid][k] = v;
    }
    __syncthreads();
    if (tid == 0) {
        double r[7];
        #pragma unroll
        for (int k = 0; k < 7; k++) {
            double v = 0.0;
            #pragma unroll
            for (int w2 = 0; w2 < 8; w2++) v += dred[w2][k];
            r[k] = v;
        }
        double n = (double)N;
        double mse = r[2] / n;
        double pred_var = (r[4] - r[3] * r[3] / n) / (n - 1.0);
        double tgt_var  = (r[6] - r[5] * r[5] / n) / (n - 1.0);
        double div = tgt_var - pred_var;
        if (div < 0.0) div = 0.0;
        long long pc = (long long)N * (N - 1) / 2;
        if (pc < 1) pc = 1;
        double rank = 0.5 * (r[0] + 0.1 * r[1]) / (double)pc;
        out[0] = (float)(0.1 * mse + 0.9 * rank + 0.1 * div);
        g_ticket = 0;  // reset for next graph replay
    }
}

extern "C" void kernel_launch(void* const* d_in, const int* in_sizes, int n_in,
                              void* d_out, int out_size) {
    const float* pred = (const float*)d_in[0];
    const float* tgt  = (const float*)d_in[1];
    float* out = (float*)d_out;
    int N = in_sizes[0];
    int nt = (N + T - 1) / T;
    dim3 grid(nt, nt);
    fused_kernel<<<grid, T>>>(pred, tgt, N, out);
}

// round 3
// speedup vs baseline: 1.8867x; 1.0748x over previous
#include <cuda_runtime.h>

// CombinedPriorityLoss: 0.1*MSE + 0.9*pairwise-rank + 0.1*diversity
// Triangle-only grid, packed f32x2 dp/dt, LOP3 sign-select, fused finalize.

#define MARGIN 0.2f

constexpr int T = 256;            // tile size == block size
constexpr int MAXT = 256;         // max tiles per dim (N <= 65536)
constexpr int MAXB = MAXT * (MAXT + 1) / 2;

__device__ float2 g_partial[MAXB];   // (accA, accB) per block
__device__ float  g_moms[MAXT][5];   // per diagonal tile: sd2, sp, spp, st, stt
__device__ unsigned g_ticket = 0;

__device__ __forceinline__ unsigned long long fadd2(unsigned long long a,
                                                    unsigned long long b) {
    unsigned long long r;
    asm("add.rn.f32x2 %0, %1, %2;" : "=l"(r) : "l"(a), "l"(b));
    return r;
}
__device__ __forceinline__ float lo32(unsigned long long v) {
    return __uint_as_float((unsigned)v);
}
__device__ __forceinline__ float hi32(unsigned long long v) {
    return __uint_as_float((unsigned)(v >> 32));
}

__global__ __launch_bounds__(T)
void fused_kernel(const float* __restrict__ pred,
                  const float* __restrict__ tgt,
                  int N, int nt, float* __restrict__ out) {
    const int bid = blockIdx.x;
    const int nblocks = gridDim.x;
    const int tid = threadIdx.x;
    const int lane = tid & 31;
    const int wid  = tid >> 5;

    // decode upper-triangle (ti <= tj), row-major by ti
    int ti = (int)((2.0 * nt + 1.0 -
                    sqrt((2.0 * nt + 1.0) * (2.0 * nt + 1.0) - 8.0 * bid)) * 0.5);
    while ((ti + 1) * nt - ((ti + 1) * ti) / 2 <= bid) ti++;
    while (ti * nt - (ti * (ti - 1)) / 2 > bid) ti--;
    const int tj = ti + (bid - (ti * nt - (ti * (ti - 1)) / 2));

    __shared__ ulonglong2 sP[T / 4];   // packed (-p) pairs: 4 j's per entry
    __shared__ ulonglong2 sT[T / 4];
    __shared__ float red[8][8];
    __shared__ int s_last;

    {
        int j = tj * T + tid;
        float pj = (j < N) ? pred[j] : 1e30f;
        float tv = (j < N) ? tgt[j]  : 1e30f;
        ((float*)sP)[tid] = -pj;
        ((float*)sT)[tid] = -tv;
    }
    __syncthreads();

    int i = ti * T + tid;
    float pi  = (i < N) ? pred[i] : 1e30f;
    float tiv = (i < N) ? tgt[i]  : 1e30f;
    unsigned long long pp, tt;
    asm("mov.b64 %0, {%1,%1};" : "=l"(pp) : "r"(__float_as_uint(pi)));
    asm("mov.b64 %0, {%1,%1};" : "=l"(tt) : "r"(__float_as_uint(tiv)));

    float accA0 = 0.f, accA1 = 0.f, accB0 = 0.f, accB1 = 0.f;

    #define PAIR(dp, dt, aA, aB) {                                            \
        unsigned qxb = __float_as_uint(dp) ^ 0x80000000u ^                    \
                       (__float_as_uint(dt) & 0x80000000u);                   \
        float r = fmaxf(__uint_as_float(qxb) + MARGIN, 0.f);                  \
        if (fabsf(dt) > MARGIN) aA += r; else aB += fabsf(dp); }

    #pragma unroll 4
    for (int k = 0; k < T / 4; k++) {
        ulonglong2 vp = sP[k];
        ulonglong2 vt = sT[k];
        unsigned long long dp01 = fadd2(pp, vp.x);
        unsigned long long dt01 = fadd2(tt, vt.x);
        unsigned long long dp23 = fadd2(pp, vp.y);
        unsigned long long dt23 = fadd2(tt, vt.y);
        PAIR(lo32(dp01), lo32(dt01), accA0, accB0);
        PAIR(hi32(dp01), hi32(dt01), accA1, accB1);
        PAIR(lo32(dp23), lo32(dt23), accA0, accB0);
        PAIR(hi32(dp23), hi32(dt23), accA1, accB1);
    }
    #undef PAIR

    float w = (ti == tj) ? 1.f : 2.f;
    float accA = (accA0 + accA1) * w;
    float accB = (accB0 + accB1) * w;

    // block reduction of accA/accB
    #pragma unroll
    for (int o = 16; o; o >>= 1) {
        accA += __shfl_down_sync(0xffffffffu, accA, o);
        accB += __shfl_down_sync(0xffffffffu, accB, o);
    }
    if (lane == 0) { red[wid][0] = accA; red[wid][1] = accB; }
    __syncthreads();
    if (tid == 0) {
        float a = 0.f, b = 0.f;
        #pragma unroll
        for (int w2 = 0; w2 < 8; w2++) { a += red[w2][0]; b += red[w2][1]; }
        g_partial[bid] = make_float2(a, b);
    }
    __syncthreads();

    // diagonal blocks: O(N) moment partials (fp32)
    if (ti == tj) {
        float p = 0.f, t = 0.f;
        if (i < N) { p = pred[i]; t = tgt[i]; }
        float d = p - t;
        float m[5] = { d * d, p, p * p, t, t * t };
        #pragma unroll
        for (int k = 0; k < 5; k++) {
            float v = m[k];
            #pragma unroll
            for (int o = 16; o; o >>= 1) v += __shfl_down_sync(0xffffffffu, v, o);
            if (lane == 0) red[wid][k] = v;
        }
        __syncthreads();
        if (tid == 0) {
            #pragma unroll
            for (int k = 0; k < 5; k++) {
                float v = 0.f;
                #pragma unroll
                for (int w2 = 0; w2 < 8; w2++) v += red[w2][k];
                g_moms[ti][k] = v;
            }
        }
    }

    // ---- deterministic last-block finalize ----
    __threadfence();
    if (tid == 0) {
        unsigned t = atomicAdd(&g_ticket, 1u);
        s_last = (t == (unsigned)(nblocks - 1));
    }
    __syncthreads();
    if (!s_last) return;

    double aA = 0.0, aB = 0.0;
    for (int b = tid; b < nblocks; b += T) {
        float2 v = g_partial[b];
        aA += (double)v.x; aB += (double)v.y;
    }
    double mm[5] = {0, 0, 0, 0, 0};
    for (int b = tid; b < nt; b += T) {
        #pragma unroll
        for (int k = 0; k < 5; k++) mm[k] += (double)g_moms[b][k];
    }

    __shared__ double dred[8][7];
    double vals[7] = { aA, aB, mm[0], mm[1], mm[2], mm[3], mm[4] };
    #pragma unroll
    for (int k = 0; k < 7; k++) {
        double v = vals[k];
        #pragma unroll
        for (int o = 16; o; o >>= 1) v += __shfl_down_sync(0xffffffffu, v, o);
        if (lane == 0) dred[wid][k] = v;
    }
    __syncthreads();
    if (tid == 0) {
        double r[7];
        #pragma unroll
        for (int k = 0; k < 7; k++) {
            double v = 0.0;
            #pragma unroll
            for (int w2 = 0; w2 < 8; w2++) v += dred[w2][k];
            r[k] = v;
        }
        double n = (double)N;
        double mse = r[2] / n;
        double pred_var = (r[4] - r[3] * r[3] / n) / (n - 1.0);
        double tgt_var  = (r[6] - r[5] * r[5] / n) / (n - 1.0);
        double div = tgt_var - pred_var;
        if (div < 0.0) div = 0.0;
        long long pc = (long long)N * (N - 1) / 2;
        if (pc < 1) pc = 1;
        double rank = 0.5 * (r[0] + 0.1 * r[1]) / (double)pc;
        out[0] = (float)(0.1 * mse + 0.9 * rank + 0.1 * div);
        g_ticket = 0;  // reset for graph replay
    }
}

extern "C" void kernel_launch(void* const* d_in, const int* in_sizes, int n_in,
                              void* d_out, int out_size) {
    const float* pred = (const float*)d_in[0];
    const float* tgt  = (const float*)d_in[1];
    float* out = (float*)d_out;
    int N = in_sizes[0];
    int nt = (N + T - 1) / T;
    int nblocks = nt * (nt + 1) / 2;
    fused_kernel<<<nblocks, T>>>(pred, tgt, N, nt, out);
}